// round 1
// baseline (speedup 1.0000x reference)
#include <cuda_runtime.h>

// Problem constants (fixed by the reference)
#define B_  64
#define T_  1024
#define E_  128
#define C_  5
#define F_  64
#define H_  2          // C/2
#define KTOT (C_ * E_) // 640

// Tiling
#define TILE_T 128
#define XROWS (TILE_T + C_ - 1)   // 132 rows of x window
#define XSTR  130                 // smem row stride (floats) -> conflict-free z reads
#define KC    32                  // K chunk held in smem for W

// Thread block: 256 threads = 16 (t-groups) x 16 (f-groups)
// Each thread computes a 4F x 8T register tile.
// smem: xs[132][130] + Ws[32][64]  = (17160 + 2048)*4 = 76832 bytes

__global__ __launch_bounds__(256, 2)
void qa_cnn_gemm_kernel(const float* __restrict__ x,
                        const float* __restrict__ W,
                        const float* __restrict__ bias,
                        float* __restrict__ out)
{
    extern __shared__ float smem[];
    float* xs = smem;                    // XROWS * XSTR
    float* Ws = smem + XROWS * XSTR;     // KC * F_

    const int b   = blockIdx.y;
    const int t0  = blockIdx.x * TILE_T;
    const int tid = threadIdx.x;
    const int tx  = tid & 15;            // t-group: covers t = t0 + tx + 16*i
    const int ty  = tid >> 4;            // f-group: covers f = ty*4 + j

    // ---- Stage x window [t0-2, t0+129] x [0,128) into smem (zero-padded) ----
    const float* xb = x + (size_t)b * T_ * E_;
    for (int idx = tid; idx < XROWS * (E_ / 4); idx += 256) {
        int row  = idx >> 5;             // / (E_/4)
        int col4 = (idx & 31) << 2;
        int t = t0 - H_ + row;
        float4 v = make_float4(0.f, 0.f, 0.f, 0.f);
        if (t >= 0 && t < T_) v = *(const float4*)(xb + (size_t)t * E_ + col4);
        float* dst = xs + row * XSTR + col4;
        dst[0] = v.x; dst[1] = v.y; dst[2] = v.z; dst[3] = v.w;
    }

    float acc[4][8];
#pragma unroll
    for (int j = 0; j < 4; ++j)
#pragma unroll
        for (int i = 0; i < 8; ++i) acc[j][i] = 0.f;

    // ---- Main K loop: 640 in chunks of 32 (never crosses a tap boundary) ----
    for (int kc = 0; kc < KTOT; kc += KC) {
        __syncthreads();   // protect Ws reuse (and xs visibility on first iter)
        // Load W chunk transposed: Ws[kk][f] = W[f][kc+kk]
        for (int idx = tid; idx < KC * F_; idx += 256) {
            int kk = idx >> 6;           // / 64
            int f  = idx & 63;
            Ws[kk * F_ + f] = W[(size_t)f * KTOT + kc + kk];
        }
        __syncthreads();

        const int c     = kc >> 7;       // tap index, constant within chunk
        const int ebase = kc & 127;      // embedding offset, constant within chunk
        const float* zb = xs + (tx + c) * XSTR + ebase;

#pragma unroll
        for (int kk = 0; kk < KC; ++kk) {
            float4 av = *(const float4*)(Ws + kk * F_ + (ty << 2));
            float a0 = av.x, a1 = av.y, a2 = av.z, a3 = av.w;
#pragma unroll
            for (int i = 0; i < 8; ++i) {
                float z = zb[kk + i * 16 * XSTR];
                acc[0][i] += a0 * z;
                acc[1][i] += a1 * z;
                acc[2][i] += a2 * z;
                acc[3][i] += a3 * z;
            }
        }
    }

    // ---- Epilogue: add bias, store out[b][f][t] ----
    const int fb = ty << 2;
    float* ob = out + ((size_t)b * F_) * T_;
#pragma unroll
    for (int j = 0; j < 4; ++j) {
        float bb = bias[fb + j];
        float* orow = ob + (size_t)(fb + j) * T_ + t0 + tx;
#pragma unroll
        for (int i = 0; i < 8; ++i) {
            orow[16 * i] = acc[j][i] + bb;
        }
    }
}

extern "C" void kernel_launch(void* const* d_in, const int* in_sizes, int n_in,
                              void* d_out, int out_size)
{
    const float* x    = (const float*)d_in[0];  // [B, T, E]
    const float* W    = (const float*)d_in[1];  // [F, C*E]
    const float* bias = (const float*)d_in[2];  // [F]
    float* out = (float*)d_out;                 // [B, F, T]

    const int smem_bytes = (XROWS * XSTR + KC * F_) * (int)sizeof(float);
    cudaFuncSetAttribute(qa_cnn_gemm_kernel,
                         cudaFuncAttributeMaxDynamicSharedMemorySize, smem_bytes);

    dim3 grid(T_ / TILE_T, B_);   // 8 x 64 = 512 blocks
    dim3 block(256);
    qa_cnn_gemm_kernel<<<grid, block, smem_bytes>>>(x, W, bias, out);
}

// round 3
// speedup vs baseline: 4.0429x; 4.0429x over previous
#include <cuda_runtime.h>
#include <cuda_bf16.h>
#include <cstdint>

// Problem constants
#define B_ 64
#define T_ 1024
#define E_ 128
#define F_ 64
#define C_ 5
#define TILE_T 128

// smem byte offsets (dynamic smem)
#define SM_BIAS 0                       // 64 floats
#define SM_AH   1024                    // 132 rows x 256B (128 bf16)   = 33792
#define SM_AL   (SM_AH + 33792)         // 33792
#define SM_BH   (SM_AL + 33792)         // 64 rows x 256B = 16384
#define SM_BL   (SM_BH + 16384)
#define SM_TOTAL (SM_BL + 16384)        // 101376 bytes -> 2 CTAs/SM

// Pre-converted W in bf16 hi/lo, [F][C*E] row-major
__device__ __align__(16) __nv_bfloat16 g_Wh[F_ * C_ * E_];
__device__ __align__(16) __nv_bfloat16 g_Wl[F_ * C_ * E_];

static __device__ __forceinline__ uint32_t smem_u32(const void* p) {
    uint32_t a;
    asm("{ .reg .u64 t; cvta.to.shared.u64 t, %1; cvt.u32.u64 %0, t; }" : "=r"(a) : "l"(p));
    return a;
}
static __device__ __forceinline__ void ldsm4(uint32_t r[4], uint32_t addr) {
    asm volatile("ldmatrix.sync.aligned.m8n8.x4.shared.b16 {%0,%1,%2,%3}, [%4];"
                 : "=r"(r[0]), "=r"(r[1]), "=r"(r[2]), "=r"(r[3]) : "r"(addr));
}
static __device__ __forceinline__ void mma_bf16(float (&d)[4], const uint32_t a[4],
                                                uint32_t b0, uint32_t b1) {
    asm volatile(
        "mma.sync.aligned.m16n8k16.row.col.f32.bf16.bf16.f32 "
        "{%0,%1,%2,%3}, {%4,%5,%6,%7}, {%8,%9}, {%0,%1,%2,%3};"
        : "+f"(d[0]), "+f"(d[1]), "+f"(d[2]), "+f"(d[3])
        : "r"(a[0]), "r"(a[1]), "r"(a[2]), "r"(a[3]), "r"(b0), "r"(b1));
}

// bf16 hi/lo split of 4 floats -> packed hi words + packed lo words
static __device__ __forceinline__ void split4(float4 v, uint32_t& h01, uint32_t& h23,
                                              uint32_t& l01, uint32_t& l23) {
    __nv_bfloat162 H0 = __floats2bfloat162_rn(v.x, v.y);
    __nv_bfloat162 H1 = __floats2bfloat162_rn(v.z, v.w);
    float rx = v.x - __low2float(H0), ry = v.y - __high2float(H0);
    float rz = v.z - __low2float(H1), rw = v.w - __high2float(H1);
    __nv_bfloat162 L0 = __floats2bfloat162_rn(rx, ry);
    __nv_bfloat162 L1 = __floats2bfloat162_rn(rz, rw);
    h01 = *(uint32_t*)&H0; h23 = *(uint32_t*)&H1;
    l01 = *(uint32_t*)&L0; l23 = *(uint32_t*)&L1;
}

// Setup kernel: W fp32 -> bf16 hi/lo (runs once per launch, trivial cost)
__global__ void convert_w_kernel(const float* __restrict__ W) {
    int idx = blockIdx.x * 256 + threadIdx.x;
    if (idx < F_ * C_ * E_) {
        float w = W[idx];
        __nv_bfloat16 h = __float2bfloat16(w);
        g_Wh[idx] = h;
        g_Wl[idx] = __float2bfloat16(w - __bfloat162float(h));
    }
}

__global__ __launch_bounds__(256, 2)
void qa_cnn_hmma_kernel(const float* __restrict__ x,
                        const float* __restrict__ bias,
                        float* __restrict__ out)
{
    extern __shared__ char smc[];
    const uint32_t sbase = smem_u32(smc);
    const int tid = threadIdx.x;
    const int wid = tid >> 5;
    const int lid = tid & 31;
    const int b   = blockIdx.y;
    const int t0  = blockIdx.x * TILE_T;

    float* bias_s = (float*)(smc + SM_BIAS);
    if (tid < F_) bias_s[tid] = bias[tid];

    // ---- stage A window once: x[b, t0-2 .. t0+129], 132 x 128 fp32 -> bf16 hi/lo ----
    const float* xb = x + (size_t)b * T_ * E_;
    for (int idx = tid; idx < 132 * 32; idx += 256) {
        int row = idx >> 5;
        int e4  = (idx & 31) << 2;           // float col (multiple of 4)
        int t   = t0 - 2 + row;
        float4 v = make_float4(0.f, 0.f, 0.f, 0.f);
        if (t >= 0 && t < T_) v = *(const float4*)(xb + (size_t)t * E_ + e4);
        uint32_t h01, h23, l01, l23;
        split4(v, h01, h23, l01, l23);
        uint32_t off = (uint32_t)row * 256u + (((uint32_t)(e4 << 1)) ^ (((uint32_t)row & 7u) << 4));
        *(uint2*)(smc + SM_AH + off) = make_uint2(h01, h23);
        *(uint2*)(smc + SM_AL + off) = make_uint2(l01, l23);
    }

    // Warp tiling: warp_m in 0..3 (32 tokens each), warp_f in 0..1 (32 filters each)
    const int warp_m = wid & 3;
    const int warp_f = wid >> 2;

    // lane-derived ldmatrix address components
    const int arow   = lid & 15;             // A: row within m16 tile
    const int achalf = lid >> 4;             // A: k-half (0/1)
    const int n_loc  = ((lid >> 4) << 3) | (lid & 7);  // B: n within 16-group
    const int bkhalf = (lid >> 3) & 1;       // B: k-half
    const int nrow   = warp_f * 32 + n_loc;
    const uint32_t b_base = sbase + SM_BH + (uint32_t)nrow * 256u;
    const uint32_t b_swz  = ((uint32_t)nrow & 7u) << 4;

    float acc[2][4][4];
#pragma unroll
    for (int m = 0; m < 2; ++m)
#pragma unroll
        for (int g = 0; g < 4; ++g)
#pragma unroll
            for (int r = 0; r < 4; ++r) acc[m][g][r] = 0.f;

    for (int c = 0; c < C_; ++c) {
        __syncthreads();   // prev tap ldmatrix done (and A/bias staged on c==0)

        // ---- stage B(tap c): copy pre-converted bf16 W slice, swizzled ----
#pragma unroll
        for (int it = 0; it < 4; ++it) {
            int idx = tid + it * 256;        // 1024 uint4 per buffer
            int f = idx >> 4;
            int u = idx & 15;                // 16B unit
            uint32_t off = (uint32_t)f * 256u + (((uint32_t)(u * 16)) ^ (((uint32_t)f & 7u) << 4));
            const __nv_bfloat16* srcH = g_Wh + (size_t)f * (C_ * E_) + c * E_ + u * 8;
            const __nv_bfloat16* srcL = g_Wl + (size_t)f * (C_ * E_) + c * E_ + u * 8;
            *(uint4*)(smc + SM_BH + off) = *(const uint4*)srcH;
            *(uint4*)(smc + SM_BL + off) = *(const uint4*)srcL;
        }
        __syncthreads();

        const int row_w = c + warp_m * 32 + arow;
        const uint32_t a_base = sbase + SM_AH + (uint32_t)row_w * 256u;
        const uint32_t a_swz  = ((uint32_t)row_w & 7u) << 4;

#pragma unroll
        for (int ks = 0; ks < 8; ++ks) {
            uint32_t aoff = ((uint32_t)(ks * 32 + achalf * 16)) ^ a_swz;
            uint32_t ah0[4], ah1[4], al0[4], al1[4];
            ldsm4(ah0, a_base + aoff);
            ldsm4(ah1, a_base + 4096u + aoff);
            ldsm4(al0, a_base + 33792u + aoff);
            ldsm4(al1, a_base + 33792u + 4096u + aoff);

            uint32_t boff = ((uint32_t)(ks * 32 + bkhalf * 16)) ^ b_swz;
            uint32_t bh0[4], bh1[4], bl0[4], bl1[4];
            ldsm4(bh0, b_base + boff);
            ldsm4(bh1, b_base + 4096u + boff);
            ldsm4(bl0, b_base + 16384u + boff);
            ldsm4(bl1, b_base + 16384u + 4096u + boff);

#pragma unroll
            for (int m = 0; m < 2; ++m) {
                const uint32_t* ah = m ? ah1 : ah0;
                const uint32_t* al = m ? al1 : al0;
#pragma unroll
                for (int g = 0; g < 4; ++g) {
                    const uint32_t* bh = (g >> 1) ? bh1 : bh0;
                    const uint32_t* bl = (g >> 1) ? bl1 : bl0;
                    int pi = (g & 1) * 2;
                    mma_bf16(acc[m][g], ah, bh[pi], bh[pi + 1]);   // hi*hi
                    mma_bf16(acc[m][g], ah, bl[pi], bl[pi + 1]);   // hi*lo
                    mma_bf16(acc[m][g], al, bh[pi], bh[pi + 1]);   // lo*hi
                }
            }
        }
    }

    // ---- epilogue: acc -> out[b][f][t] + bias ----
    const int tb  = t0 + warp_m * 32 + (lid >> 2);
    const int fb0 = warp_f * 32 + (lid & 3) * 2;
    float* ob = out + (size_t)b * F_ * T_;
#pragma unroll
    for (int m = 0; m < 2; ++m) {
#pragma unroll
        for (int g = 0; g < 4; ++g) {
            int f = fb0 + (g >> 1) * 16 + (g & 1) * 8;
            int t = tb + m * 16;
            float bf0 = bias_s[f], bf1 = bias_s[f + 1];
            ob[(size_t)f * T_ + t]           = acc[m][g][0] + bf0;
            ob[(size_t)(f + 1) * T_ + t]     = acc[m][g][1] + bf1;
            ob[(size_t)f * T_ + t + 8]       = acc[m][g][2] + bf0;
            ob[(size_t)(f + 1) * T_ + t + 8] = acc[m][g][3] + bf1;
        }
    }
}

extern "C" void kernel_launch(void* const* d_in, const int* in_sizes, int n_in,
                              void* d_out, int out_size)
{
    const float* x    = (const float*)d_in[0];  // [B, T, E]
    const float* W    = (const float*)d_in[1];  // [F, C*E]
    const float* bias = (const float*)d_in[2];  // [F]
    float* out = (float*)d_out;                 // [B, F, T]

    convert_w_kernel<<<(F_ * C_ * E_ + 255) / 256, 256>>>(W);

    cudaFuncSetAttribute(qa_cnn_hmma_kernel,
                         cudaFuncAttributeMaxDynamicSharedMemorySize, SM_TOTAL);
    dim3 grid(T_ / TILE_T, B_);   // 8 x 64 = 512 CTAs
    qa_cnn_hmma_kernel<<<grid, 256, SM_TOTAL>>>(x, bias, out);
}

// round 4
// speedup vs baseline: 6.9835x; 1.7274x over previous
#include <cuda_runtime.h>
#include <cuda_fp16.h>
#include <cstdint>

// Problem constants
#define B_ 64
#define T_ 1024
#define E_ 128
#define F_ 64
#define C_ 5
#define TILE_T 128

// smem layout (dynamic)
#define SM_BIAS 0                       // 64 floats (256B)
#define SM_A    1024                    // 132 rows x 256B (128 fp16) = 33792
#define SM_B    (SM_A + 33792)          // 64 rows x 256B = 16384
#define SM_TOTAL (SM_B + 16384)         // 51200 bytes -> 3-4 CTAs/SM

// Pre-converted W in fp16, [F][C*E] row-major
__device__ __align__(16) __half g_Wf16[F_ * C_ * E_];

static __device__ __forceinline__ uint32_t smem_u32(const void* p) {
    uint32_t a;
    asm("{ .reg .u64 t; cvta.to.shared.u64 t, %1; cvt.u32.u64 %0, t; }" : "=r"(a) : "l"(p));
    return a;
}
static __device__ __forceinline__ void ldsm4(uint32_t r[4], uint32_t addr) {
    asm volatile("ldmatrix.sync.aligned.m8n8.x4.shared.b16 {%0,%1,%2,%3}, [%4];"
                 : "=r"(r[0]), "=r"(r[1]), "=r"(r[2]), "=r"(r[3]) : "r"(addr));
}
static __device__ __forceinline__ void mma_fp16(float (&d)[4], const uint32_t a[4],
                                                uint32_t b0, uint32_t b1) {
    asm volatile(
        "mma.sync.aligned.m16n8k16.row.col.f32.f16.f16.f32 "
        "{%0,%1,%2,%3}, {%4,%5,%6,%7}, {%8,%9}, {%0,%1,%2,%3};"
        : "+f"(d[0]), "+f"(d[1]), "+f"(d[2]), "+f"(d[3])
        : "r"(a[0]), "r"(a[1]), "r"(a[2]), "r"(a[3]), "r"(b0), "r"(b1));
}

// Setup kernel: W fp32 -> fp16 (trivial, once per launch)
__global__ void convert_w_kernel(const float* __restrict__ W) {
    int idx = blockIdx.x * 256 + threadIdx.x;
    if (idx < F_ * C_ * E_) g_Wf16[idx] = __float2half_rn(W[idx]);
}

__global__ __launch_bounds__(256, 3)
void qa_cnn_hmma_kernel(const float* __restrict__ x,
                        const float* __restrict__ bias,
                        float* __restrict__ out)
{
    extern __shared__ char smc[];
    const uint32_t sbase = smem_u32(smc);
    const int tid = threadIdx.x;
    const int wid = tid >> 5;
    const int lid = tid & 31;
    const int b   = blockIdx.y;
    const int t0  = blockIdx.x * TILE_T;

    float* bias_s = (float*)(smc + SM_BIAS);
    if (tid < F_) bias_s[tid] = bias[tid];

    // ---- stage A window once: x[b, t0-2 .. t0+129], 132 x 128 fp32 -> fp16 ----
    const float* xb = x + (size_t)b * T_ * E_;
    for (int idx = tid; idx < 132 * 32; idx += 256) {
        int row = idx >> 5;
        int e4  = (idx & 31) << 2;           // float col (multiple of 4)
        int t   = t0 - 2 + row;
        float4 v = make_float4(0.f, 0.f, 0.f, 0.f);
        if (t >= 0 && t < T_) v = *(const float4*)(xb + (size_t)t * E_ + e4);
        __half2 p0 = __floats2half2_rn(v.x, v.y);
        __half2 p1 = __floats2half2_rn(v.z, v.w);
        uint32_t off = (uint32_t)row * 256u +
                       (((uint32_t)(e4 << 1)) ^ (((uint32_t)row & 7u) << 4));
        *(uint2*)(smc + SM_A + off) = make_uint2(*(uint32_t*)&p0, *(uint32_t*)&p1);
    }

    // Warp tiling: warp_m 0..3 (32 tokens), warp_f 0..1 (32 filters)
    const int warp_m = wid & 3;
    const int warp_f = wid >> 2;

    const int arow   = lid & 15;
    const int achalf = lid >> 4;
    const int n_loc  = ((lid >> 4) << 3) | (lid & 7);
    const int bkhalf = (lid >> 3) & 1;
    const int nrow   = warp_f * 32 + n_loc;
    const uint32_t b_base = sbase + SM_B + (uint32_t)nrow * 256u;
    const uint32_t b_swz  = ((uint32_t)nrow & 7u) << 4;

    float acc[2][4][4];
#pragma unroll
    for (int m = 0; m < 2; ++m)
#pragma unroll
        for (int g = 0; g < 4; ++g)
#pragma unroll
            for (int r = 0; r < 4; ++r) acc[m][g][r] = 0.f;

    for (int c = 0; c < C_; ++c) {
        __syncthreads();   // prev-tap ldmatrix done (and A/bias staged on c==0)

        // ---- stage B(tap c): pre-converted fp16 W slice, swizzled ----
#pragma unroll
        for (int it = 0; it < 4; ++it) {
            int idx = tid + it * 256;        // 1024 uint4
            int f = idx >> 4;
            int u = idx & 15;                // 16B unit
            uint32_t off = (uint32_t)f * 256u +
                           (((uint32_t)(u * 16)) ^ (((uint32_t)f & 7u) << 4));
            *(uint4*)(smc + SM_B + off) =
                *(const uint4*)(g_Wf16 + (size_t)f * (C_ * E_) + c * E_ + u * 8);
        }
        __syncthreads();

        const int row_w = c + warp_m * 32 + arow;
        const uint32_t a_base = sbase + SM_A + (uint32_t)row_w * 256u;
        const uint32_t a_swz  = ((uint32_t)row_w & 7u) << 4;

#pragma unroll
        for (int ks = 0; ks < 8; ++ks) {
            uint32_t aoff = ((uint32_t)(ks * 32 + achalf * 16)) ^ a_swz;
            uint32_t a0[4], a1[4];
            ldsm4(a0, a_base + aoff);
            ldsm4(a1, a_base + 4096u + aoff);

            uint32_t boff = ((uint32_t)(ks * 32 + bkhalf * 16)) ^ b_swz;
            uint32_t b0[4], b1[4];
            ldsm4(b0, b_base + boff);
            ldsm4(b1, b_base + 4096u + boff);

#pragma unroll
            for (int m = 0; m < 2; ++m) {
                const uint32_t* am = m ? a1 : a0;
#pragma unroll
                for (int g = 0; g < 4; ++g) {
                    const uint32_t* bg = (g >> 1) ? b1 : b0;
                    int pi = (g & 1) * 2;
                    mma_fp16(acc[m][g], am, bg[pi], bg[pi + 1]);
                }
            }
        }
    }

    // ---- epilogue: acc -> out[b][f][t] + bias ----
    const int tb  = t0 + warp_m * 32 + (lid >> 2);
    const int fb0 = warp_f * 32 + (lid & 3) * 2;
    float* ob = out + (size_t)b * F_ * T_;
#pragma unroll
    for (int m = 0; m < 2; ++m) {
#pragma unroll
        for (int g = 0; g < 4; ++g) {
            int f = fb0 + (g >> 1) * 16 + (g & 1) * 8;
            int t = tb + m * 16;
            float bf0 = bias_s[f], bf1 = bias_s[f + 1];
            ob[(size_t)f * T_ + t]           = acc[m][g][0] + bf0;
            ob[(size_t)(f + 1) * T_ + t]     = acc[m][g][1] + bf1;
            ob[(size_t)f * T_ + t + 8]       = acc[m][g][2] + bf0;
            ob[(size_t)(f + 1) * T_ + t + 8] = acc[m][g][3] + bf1;
        }
    }
}

extern "C" void kernel_launch(void* const* d_in, const int* in_sizes, int n_in,
                              void* d_out, int out_size)
{
    const float* x    = (const float*)d_in[0];  // [B, T, E]
    const float* W    = (const float*)d_in[1];  // [F, C*E]
    const float* bias = (const float*)d_in[2];  // [F]
    float* out = (float*)d_out;                 // [B, F, T]

    convert_w_kernel<<<(F_ * C_ * E_ + 255) / 256, 256>>>(W);

    cudaFuncSetAttribute(qa_cnn_hmma_kernel,
                         cudaFuncAttributeMaxDynamicSharedMemorySize, SM_TOTAL);
    dim3 grid(T_ / TILE_T, B_);   // 8 x 64 = 512 CTAs
    qa_cnn_hmma_kernel<<<grid, 256, SM_TOTAL>>>(x, bias, out);
}